// round 15
// baseline (speedup 1.0000x reference)
#include <cuda_runtime.h>

#define NT 5
#define A_FIX 128
#define THREADS 256
#define MAXP 74            // atom-pairs: 64 + up to 2 pad-pairs per bucket
#define NWARPS (THREADS / 32)

typedef unsigned long long ull;

__device__ __forceinline__ float fast_sqrt(float x) {
    float r; asm("sqrt.approx.f32 %0, %1;" : "=f"(r) : "f"(x)); return r;
}
__device__ __forceinline__ float fast_ex2(float x) {
    float r; asm("ex2.approx.f32 %0, %1;" : "=f"(r) : "f"(x)); return r;
}
__device__ __forceinline__ float fast_rcp(float x) {
    float r; asm("rcp.approx.f32 %0, %1;" : "=f"(r) : "f"(x)); return r;
}
__device__ __forceinline__ float fast_rsq(float x) {
    float r; asm("rsqrt.approx.f32 %0, %1;" : "=f"(r) : "f"(x)); return r;
}

__device__ __forceinline__ ull pack2(float lo, float hi) {
    ull r;
    asm("mov.b64 %0, {%1, %2};" : "=l"(r) : "r"(__float_as_uint(lo)), "r"(__float_as_uint(hi)));
    return r;
}
__device__ __forceinline__ void unpack2(ull v, float& lo, float& hi) {
    unsigned int a, b;
    asm("mov.b64 {%0, %1}, %2;" : "=r"(a), "=r"(b) : "l"(v));
    lo = __uint_as_float(a); hi = __uint_as_float(b);
}
__device__ __forceinline__ ull ffma2(ull a, ull b, ull c) {
    ull d; asm("fma.rn.f32x2 %0, %1, %2, %3;" : "=l"(d) : "l"(a), "l"(b), "l"(c)); return d;
}
__device__ __forceinline__ ull fadd2(ull a, ull b) {
    ull d; asm("add.rn.f32x2 %0, %1, %2;" : "=l"(d) : "l"(a), "l"(b)); return d;
}

// one atom-PAIR vs this thread's point; accumulates into one bank
// xy = (x_a,x_b | y_a,y_b), zw = (z_a,z_b | w_a,w_b), w = |L*c|^2
#define PAIRA(xy, zw, SW, SX, SY, SZ)                                          \
    {                                                                          \
        ull dot = ffma2((xy).x, nq2x, ffma2((xy).y, nq2y,                      \
                     ffma2((zw).x, nq2z, nqq2)));   /* -2c.q + |q|^2 */        \
        ull d2p = fadd2((zw).y, dot);               /* |c-q|^2 both atoms */   \
        float d0, d1; unpack2(d2p, d0, d1);                                    \
        float e0 = fast_ex2(-fast_sqrt(fabsf(d0)));                            \
        float e1 = fast_ex2(-fast_sqrt(fabsf(d1)));                            \
        ull e2 = pack2(e0, e1);                                                \
        SW = fadd2(SW, e2);                                                    \
        SX = ffma2(e2, (xy).x, SX);                                            \
        SY = ffma2(e2, (xy).y, SY);                                            \
        SZ = ffma2(e2, (zw).x, SZ);                                            \
    }

__global__ void gnf_kernel(
    const float* __restrict__ coords,    // [B, A, 3]
    const int*   __restrict__ atom_types,// [B, A]
    const float* __restrict__ query,     // [B, P, 3]
    float*       __restrict__ out,       // [B, P, NT, 3]
    int P)
{
    // interleaved atom-pair SoA, all 5 buckets back-to-back (padded):
    // sAT[8j..8j+7] = (xa,xb,ya,yb,za,zb,wa,wb)
    __shared__ __align__(16) float sAT[MAXP * 8];
    __shared__ int cnt[NT];
    __shared__ int offp[NT + 1];
    __shared__ int wbase[NWARPS][NT];

    const int b    = blockIdx.y;
    const int tid  = threadIdx.x;
    const int lane = tid & 31;
    const int wid  = tid >> 5;
    const float L  = 1.4426950408889634f;   // log2(e)

    // ---- init: counters + sentinel fill (w = 1e30 -> e == 0 exactly) ----
    if (tid < NT) cnt[tid] = 0;
    for (int i = tid; i < MAXP * 8; i += THREADS)
        sAT[i] = ((i & 7) >= 6) ? 1e30f : 0.0f;
    __syncthreads();

    // ---- 5-type ballot bucketing, 1 atomic per (warp, type) ----
    const int myT = (tid < A_FIX) ? atom_types[b * A_FIX + tid] : -1;
    int rankw = 0;
    #pragma unroll
    for (int t = 0; t < NT; t++) {
        unsigned m = __ballot_sync(0xFFFFFFFFu, myT == t);
        if (lane == 0) wbase[wid][t] = m ? atomicAdd(&cnt[t], __popc(m)) : 0;
        if (myT == t) rankw = __popc(m & ((1u << lane) - 1u));
    }
    __syncthreads();
    if (tid == 0) {
        int s = 0;
        #pragma unroll
        for (int t = 0; t < NT; t++) { offp[t] = s; s += (cnt[t] + 3) & ~3; }
        offp[NT] = s;
    }
    __syncthreads();
    if (myT >= 0 && myT < NT) {
        int r = offp[myT] + wbase[wid][myT] + rankw;
        const float* c = coords + (b * A_FIX + tid) * 3;
        float x = c[0] * L, y = c[1] * L, z = c[2] * L;
        float w = fmaf(x, x, fmaf(y, y, z * z));
        int j = r >> 1, h = r & 1;
        sAT[8 * j + h]     = x;
        sAT[8 * j + 2 + h] = y;
        sAT[8 * j + 4 + h] = z;
        sAT[8 * j + 6 + h] = w;
    }
    __syncthreads();

    // ---- main: one point per thread, all 5 types ----
    const int p = blockIdx.x * THREADS + tid;
    if (p >= P) return;

    const float* q = query + ((long)b * P + p) * 3;
    const float qx = q[0] * L, qy = q[1] * L, qz = q[2] * L;
    const float qq = fmaf(qx, qx, fmaf(qy, qy, qz * qz));   // +|qL|^2

    const ull nq2x = pack2(-2.0f * qx, -2.0f * qx);
    const ull nq2y = pack2(-2.0f * qy, -2.0f * qy);
    const ull nq2z = pack2(-2.0f * qz, -2.0f * qz);
    const ull nqq2 = pack2(qq, qq);

    const ulonglong2* pA = (const ulonglong2*)sAT;
    const float INVL = 0.6931471805599453f;  // ln(2)

    float* o = out + ((long)b * P + p) * (NT * 3);

    #pragma unroll
    for (int t = 0; t < NT; t++) {
        const int kbeg = offp[t] >> 1;      // pair index, even
        const int kend = offp[t + 1] >> 1;  // padded: (kend-kbeg) % 2 == 0

        // 2 banks -> 4 independent MUFU chains
        ull wA = 0, xA = 0, yA = 0, zA = 0;
        ull wB = 0, xB = 0, yB = 0, zB = 0;

        for (int j = kbeg; j < kend; j += 2) {
            ulonglong2 xy0 = pA[2 * j],     zw0 = pA[2 * j + 1];
            ulonglong2 xy1 = pA[2 * j + 2], zw1 = pA[2 * j + 3];
            PAIRA(xy0, zw0, wA, xA, yA, zA);
            PAIRA(xy1, zw1, wB, xB, yB, zB);
        }

        ull sw2 = fadd2(wA, wB);
        ull sx2 = fadd2(xA, xB);
        ull sy2 = fadd2(yA, yB);
        ull sz2 = fadd2(zA, zB);

        float swl, swh, sxl, sxh, syl, syh, szl, szh;
        unpack2(sw2, swl, swh);
        unpack2(sx2, sxl, sxh);
        unpack2(sy2, syl, syh);
        unpack2(sz2, szl, szh);
        float sw = swl + swh, sxc = sxl + sxh, syc = syl + syh, szc = szl + szh;

        float gx = 0.f, gy = 0.f, gz = 0.f;
        if (cnt[t] > 0) {
            float inv = fast_rcp(sw) * INVL;          // un-scale by L
            gx = (sxc - qx * sw) * inv;               // sum e*(cx-qx) / sum e
            gy = (syc - qy * sw) * inv;
            gz = (szc - qz * sw) * inv;
            float g2 = fmaf(gx, gx, fmaf(gy, gy, gz * gz));
            float f = fminf(1.0f, 0.3f * fast_rsq(fmaxf(g2, 1e-24f)));
            gx *= f; gy *= f; gz *= f;
        }
        o[t * 3 + 0] = gx;
        o[t * 3 + 1] = gy;
        o[t * 3 + 2] = gz;
    }
}

extern "C" void kernel_launch(void* const* d_in, const int* in_sizes, int n_in,
                              void* d_out, int out_size)
{
    const float* coords     = (const float*)d_in[0];  // B*A*3
    const int*   atom_types = (const int*)  d_in[1];  // B*A
    const float* query      = (const float*)d_in[2];  // B*P*3

    const int A = A_FIX;
    const int B = in_sizes[1] / A;
    const int P = in_sizes[2] / (3 * B);

    dim3 grid((P + THREADS - 1) / THREADS, B);
    gnf_kernel<<<grid, THREADS>>>(coords, atom_types, query, (float*)d_out, P);
}